// round 1
// baseline (speedup 1.0000x reference)
#include <cuda_runtime.h>
#include <cstdint>

#define N        100000
#define FIN      512
#define HID      512
#define C        40
#define EDG      1600000
#define KITER    10
#define ALPHA    0.1f

// ---------------- scratch (device globals; no allocation allowed) ----------
__device__ float g_Z0[(size_t)N * C];   // MLP output z0
__device__ float g_ZA[(size_t)N * C];   // ping
__device__ float g_ZB[(size_t)N * C];   // pong
__device__ float g_dinv[N];
__device__ float g_w[EDG];
__device__ int   g_deg[N];

// ---------------- degree / normalization ----------------------------------
__global__ void k_deg_init() {
    int i = blockIdx.x * blockDim.x + threadIdx.x;
    if (i < N) g_deg[i] = 1;   // self-loop
}

__global__ void k_deg_count(const int* __restrict__ ei) {
    int e = blockIdx.x * blockDim.x + threadIdx.x;
    if (e < EDG) atomicAdd(&g_deg[ei[e]], 1);   // ei[e] = row (target)
}

__global__ void k_dinv() {
    int i = blockIdx.x * blockDim.x + threadIdx.x;
    if (i < N) g_dinv[i] = rsqrtf((float)g_deg[i]);
}

__global__ void k_w(const int* __restrict__ ei) {
    int e = blockIdx.x * blockDim.x + threadIdx.x;
    if (e < EDG) {
        int r = ei[e];
        int s = ei[EDG + e];
        g_w[e] = (1.0f - ALPHA) * g_dinv[r] * g_dinv[s];
    }
}

// ---------------- fused MLP: z0 = relu(x@W1+b1)@W2 + b2 -------------------
#define BM 128
#define BK 16
#define BH 128
#define TPB 256

// shared carve: xs[BK][BM+4] | ws[BK][BH] | hs[BM][BH+4] | w2s[BH][C]
#define XS_STRIDE (BM + 4)
#define HS_STRIDE (BH + 4)
#define SM_XS  0
#define SM_WS  (SM_XS + BK * XS_STRIDE)
#define SM_HS  (SM_WS + BK * BH)
#define SM_W2  (SM_HS + BM * HS_STRIDE)
#define SM_TOT (SM_W2 + BH * C)
#define GEMM_SMEM_BYTES (SM_TOT * 4)

__global__ void __launch_bounds__(TPB)
k_gemm(const float* __restrict__ x,  const float* __restrict__ W1,
       const float* __restrict__ b1, const float* __restrict__ W2,
       const float* __restrict__ b2, float* __restrict__ z0)
{
    extern __shared__ float sm[];
    float* xs  = sm + SM_XS;
    float* wsm = sm + SM_WS;
    float* hs  = sm + SM_HS;
    float* w2s = sm + SM_W2;

    const int tid  = threadIdx.x;
    const int tx   = tid & 15;          // 0..15, hidden-col micro-tile
    const int ty   = tid >> 4;          // 0..15, row micro-tile
    const int row0 = blockIdx.x * BM;

    // mini-gemm mapping: 32 row-groups x 8 col-groups
    const int rb = (tid >> 3) * 4;      // 4 rows
    const int cb = (tid & 7) * 5;       // 5 classes

    float zacc[4][5];
    #pragma unroll
    for (int i = 0; i < 4; i++)
        #pragma unroll
        for (int c = 0; c < 5; c++) zacc[i][c] = 0.0f;

    for (int ch = 0; ch < HID / BH; ch++) {
        const int hb = ch * BH;

        __syncthreads();   // protect hs/w2s readers from previous chunk

        // load W2 chunk (rows hb..hb+BH are contiguous in row-major [HID][C])
        for (int i = tid; i < BH * C; i += TPB)
            w2s[i] = W2[hb * C + i];

        float acc[8][8];
        #pragma unroll
        for (int i = 0; i < 8; i++)
            #pragma unroll
            for (int j = 0; j < 8; j++) acc[i][j] = 0.0f;

        float4 xr0, xr1, wr0, wr1;

        // ---- prefetch tile 0 ----
        {
            int kb = 0;
            int f = tid;       { int r = f >> 2, k4 = f & 3; int gr = row0 + r;
                xr0 = (gr < N) ? *(const float4*)(x + (size_t)gr * FIN + kb + k4 * 4)
                               : make_float4(0.f, 0.f, 0.f, 0.f); }
            f = TPB + tid;     { int r = f >> 2, k4 = f & 3; int gr = row0 + r;
                xr1 = (gr < N) ? *(const float4*)(x + (size_t)gr * FIN + kb + k4 * 4)
                               : make_float4(0.f, 0.f, 0.f, 0.f); }
            f = tid;           { int k = f >> 5, c4 = f & 31;
                wr0 = *(const float4*)(W1 + (size_t)(kb + k) * HID + hb + c4 * 4); }
            f = TPB + tid;     { int k = f >> 5, c4 = f & 31;
                wr1 = *(const float4*)(W1 + (size_t)(kb + k) * HID + hb + c4 * 4); }
        }

        for (int kt = 0; kt < FIN / BK; kt++) {
            __syncthreads();   // previous compute done before smem overwrite

            // store prefetched regs -> smem (x transposed)
            {
                int f = tid;     int r = f >> 2, k4 = f & 3;
                xs[(k4 * 4 + 0) * XS_STRIDE + r] = xr0.x;
                xs[(k4 * 4 + 1) * XS_STRIDE + r] = xr0.y;
                xs[(k4 * 4 + 2) * XS_STRIDE + r] = xr0.z;
                xs[(k4 * 4 + 3) * XS_STRIDE + r] = xr0.w;
                f = TPB + tid;   r = f >> 2; k4 = f & 3;
                xs[(k4 * 4 + 0) * XS_STRIDE + r] = xr1.x;
                xs[(k4 * 4 + 1) * XS_STRIDE + r] = xr1.y;
                xs[(k4 * 4 + 2) * XS_STRIDE + r] = xr1.z;
                xs[(k4 * 4 + 3) * XS_STRIDE + r] = xr1.w;
                f = tid;        *(float4*)&wsm[(f >> 5) * BH + (f & 31) * 4] = wr0;
                f = TPB + tid;  *(float4*)&wsm[(f >> 5) * BH + (f & 31) * 4] = wr1;
            }
            __syncthreads();

            // prefetch next tile
            if (kt + 1 < FIN / BK) {
                int kb = (kt + 1) * BK;
                int f = tid;       { int r = f >> 2, k4 = f & 3; int gr = row0 + r;
                    xr0 = (gr < N) ? *(const float4*)(x + (size_t)gr * FIN + kb + k4 * 4)
                                   : make_float4(0.f, 0.f, 0.f, 0.f); }
                f = TPB + tid;     { int r = f >> 2, k4 = f & 3; int gr = row0 + r;
                    xr1 = (gr < N) ? *(const float4*)(x + (size_t)gr * FIN + kb + k4 * 4)
                                   : make_float4(0.f, 0.f, 0.f, 0.f); }
                f = tid;           { int k = f >> 5, c4 = f & 31;
                    wr0 = *(const float4*)(W1 + (size_t)(kb + k) * HID + hb + c4 * 4); }
                f = TPB + tid;     { int k = f >> 5, c4 = f & 31;
                    wr1 = *(const float4*)(W1 + (size_t)(kb + k) * HID + hb + c4 * 4); }
            }

            // compute
            #pragma unroll
            for (int k = 0; k < BK; k++) {
                float a[8], b[8];
                *(float4*)&a[0] = *(const float4*)&xs[k * XS_STRIDE + ty * 8];
                *(float4*)&a[4] = *(const float4*)&xs[k * XS_STRIDE + ty * 8 + 4];
                *(float4*)&b[0] = *(const float4*)&wsm[k * BH + tx * 8];
                *(float4*)&b[4] = *(const float4*)&wsm[k * BH + tx * 8 + 4];
                #pragma unroll
                for (int i = 0; i < 8; i++)
                    #pragma unroll
                    for (int j = 0; j < 8; j++)
                        acc[i][j] = fmaf(a[i], b[j], acc[i][j]);
            }
        }

        // bias + relu -> hs
        float bv[8];
        #pragma unroll
        for (int j = 0; j < 8; j++) bv[j] = b1[hb + tx * 8 + j];
        #pragma unroll
        for (int i = 0; i < 8; i++)
            #pragma unroll
            for (int j = 0; j < 8; j++)
                hs[(ty * 8 + i) * HS_STRIDE + tx * 8 + j] =
                    fmaxf(acc[i][j] + bv[j], 0.0f);
        __syncthreads();

        // mini-gemm: zacc += hs[128,BH] @ w2s[BH,40]
        #pragma unroll 4
        for (int k = 0; k < BH; k++) {
            float h0 = hs[(rb + 0) * HS_STRIDE + k];
            float h1 = hs[(rb + 1) * HS_STRIDE + k];
            float h2 = hs[(rb + 2) * HS_STRIDE + k];
            float h3 = hs[(rb + 3) * HS_STRIDE + k];
            #pragma unroll
            for (int c = 0; c < 5; c++) {
                float wv = w2s[k * C + cb + c];
                zacc[0][c] = fmaf(h0, wv, zacc[0][c]);
                zacc[1][c] = fmaf(h1, wv, zacc[1][c]);
                zacc[2][c] = fmaf(h2, wv, zacc[2][c]);
                zacc[3][c] = fmaf(h3, wv, zacc[3][c]);
            }
        }
    }

    // epilogue: + b2, store z0
    float b2v[5];
    #pragma unroll
    for (int c = 0; c < 5; c++) b2v[c] = b2[cb + c];
    #pragma unroll
    for (int i = 0; i < 4; i++) {
        int r = row0 + rb + i;
        if (r < N) {
            #pragma unroll
            for (int c = 0; c < 5; c++)
                z0[(size_t)r * C + cb + c] = zacc[i][c] + b2v[c];
        }
    }
}

// ---------------- APPNP iteration ------------------------------------------
// out = ALPHA*z0 + 0.9*dinv^2*zp   (self-loop folded in)
__global__ void k_init(const float* __restrict__ zp, float* __restrict__ out) {
    int i = blockIdx.x * blockDim.x + threadIdx.x;   // over N*C/4 float4s
    if (i >= N * C / 4) return;
    int node = i / (C / 4);
    float d = g_dinv[node];
    float s = (1.0f - ALPHA) * d * d;
    float4 z0v = ((const float4*)g_Z0)[i];
    float4 zv  = ((const float4*)zp)[i];
    float4 o;
    o.x = ALPHA * z0v.x + s * zv.x;
    o.y = ALPHA * z0v.y + s * zv.y;
    o.z = ALPHA * z0v.z + s * zv.z;
    o.w = ALPHA * z0v.w + s * zv.w;
    ((float4*)out)[i] = o;
}

// out[row] += w_e * zp[col]  (vectorized reduction, 10 float4 chunks per edge)
__global__ void k_edge(const int* __restrict__ ei, const float* __restrict__ zp,
                       float* __restrict__ out) {
    unsigned idx = blockIdx.x * blockDim.x + threadIdx.x;   // over EDG*10
    if (idx >= (unsigned)EDG * 10u) return;
    unsigned e = idx / 10u;
    unsigned c = idx - e * 10u;
    int r = ei[e];
    int s = ei[EDG + e];
    float w = g_w[e];
    float4 v = *(const float4*)(zp + (size_t)s * C + c * 4);
    float4 m;
    m.x = v.x * w; m.y = v.y * w; m.z = v.z * w; m.w = v.w * w;
    float* dst = out + (size_t)r * C + c * 4;
    asm volatile("red.global.add.v4.f32 [%0], {%1,%2,%3,%4};"
                 :: "l"(dst), "f"(m.x), "f"(m.y), "f"(m.z), "f"(m.w)
                 : "memory");
}

// ---------------- launch ----------------------------------------------------
extern "C" void kernel_launch(void* const* d_in, const int* in_sizes, int n_in,
                              void* d_out, int out_size) {
    const float* x  = (const float*)d_in[0];
    const float* W1 = (const float*)d_in[1];
    const float* b1 = (const float*)d_in[2];
    const float* W2 = (const float*)d_in[3];
    const float* b2 = (const float*)d_in[4];
    const int*   ei = (const int*)  d_in[5];
    float* out = (float*)d_out;

    float *Z0, *ZA, *ZB;
    cudaGetSymbolAddress((void**)&Z0, g_Z0);
    cudaGetSymbolAddress((void**)&ZA, g_ZA);
    cudaGetSymbolAddress((void**)&ZB, g_ZB);

    // normalization
    k_deg_init <<<(N + 255) / 256, 256>>>();
    k_deg_count<<<(EDG + 255) / 256, 256>>>(ei);
    k_dinv     <<<(N + 255) / 256, 256>>>();
    k_w        <<<(EDG + 255) / 256, 256>>>(ei);

    // fused MLP
    cudaFuncSetAttribute(k_gemm, cudaFuncAttributeMaxDynamicSharedMemorySize,
                         GEMM_SMEM_BYTES);
    k_gemm<<<(N + BM - 1) / BM, TPB, GEMM_SMEM_BYTES>>>(x, W1, b1, W2, b2, Z0);

    // APPNP, K iterations; last iteration writes d_out directly
    const float* zp = Z0;
    for (int it = 1; it <= KITER; it++) {
        float* tgt = (it == KITER) ? out : ((it & 1) ? ZA : ZB);
        k_init<<<(N * C / 4 + 255) / 256, 256>>>(zp, tgt);
        k_edge<<<((unsigned)EDG * 10u + 255) / 256, 256>>>(ei, zp, tgt);
        zp = tgt;
    }
}

// round 2
// speedup vs baseline: 1.1467x; 1.1467x over previous
#include <cuda_runtime.h>
#include <cstdint>

#define N        100000
#define FIN      512
#define HID      512
#define C        40
#define EDG      1600000
#define KITER    10
#define ALPHA    0.1f

// ---------------- scratch (device globals; no allocation allowed) ----------
__device__ float g_Z0[(size_t)N * C];   // MLP output z0
__device__ float g_ZA[(size_t)N * C];   // ping
__device__ float g_ZB[(size_t)N * C];   // pong
__device__ float g_dinv[N];
__device__ int   g_deg[N];              // includes self-loop (+1)
__device__ int   g_base[N];             // CSR segment base (real edges only)
__device__ int   g_cursor[N];
__device__ int2  g_meta[EDG];           // {col, bits(w)}
__device__ int   g_total;

// ---------------- setup ----------------------------------------------------
__global__ void k_reset() {
    int i = blockIdx.x * blockDim.x + threadIdx.x;
    if (i < N) g_deg[i] = 1;           // self-loop
    if (i == 0) g_total = 0;
}

__global__ void k_deg_count(const int* __restrict__ ei) {
    int e = blockIdx.x * blockDim.x + threadIdx.x;
    if (e < EDG) atomicAdd(&g_deg[ei[e]], 1);   // ei[e] = row (target)
}

__global__ void k_dinv_base() {
    int i = blockIdx.x * blockDim.x + threadIdx.x;
    if (i < N) {
        int d = g_deg[i];
        g_dinv[i] = rsqrtf((float)d);
        g_base[i] = atomicAdd(&g_total, d - 1);   // real-edge segment
    }
}

__global__ void k_cursor() {
    int i = blockIdx.x * blockDim.x + threadIdx.x;
    if (i < N) g_cursor[i] = g_base[i];
}

__global__ void k_scatter(const int* __restrict__ ei) {
    int e = blockIdx.x * blockDim.x + threadIdx.x;
    if (e < EDG) {
        int r = ei[e];
        int s = ei[EDG + e];
        float w = (1.0f - ALPHA) * g_dinv[r] * g_dinv[s];
        int pos = atomicAdd(&g_cursor[r], 1);
        g_meta[pos] = make_int2(s, __float_as_int(w));
    }
}

// ---------------- fused MLP: z0 = relu(x@W1+b1)@W2 + b2 -------------------
#define BM 128
#define BK 16
#define BH 128
#define TPB 256

#define XS_STRIDE (BM + 4)
#define HS_STRIDE (BH + 4)
#define SM_XS  0
#define SM_WS  (SM_XS + BK * XS_STRIDE)
#define SM_HS  (SM_WS + BK * BH)
#define SM_W2  (SM_HS + BM * HS_STRIDE)
#define SM_TOT (SM_W2 + BH * C)
#define GEMM_SMEM_BYTES (SM_TOT * 4)

__global__ void __launch_bounds__(TPB)
k_gemm(const float* __restrict__ x,  const float* __restrict__ W1,
       const float* __restrict__ b1, const float* __restrict__ W2,
       const float* __restrict__ b2, float* __restrict__ z0)
{
    extern __shared__ float sm[];
    float* xs  = sm + SM_XS;
    float* wsm = sm + SM_WS;
    float* hs  = sm + SM_HS;
    float* w2s = sm + SM_W2;

    const int tid  = threadIdx.x;
    const int tx   = tid & 15;
    const int ty   = tid >> 4;
    const int row0 = blockIdx.x * BM;

    const int rb = (tid >> 3) * 4;
    const int cb = (tid & 7) * 5;

    float zacc[4][5];
    #pragma unroll
    for (int i = 0; i < 4; i++)
        #pragma unroll
        for (int c = 0; c < 5; c++) zacc[i][c] = 0.0f;

    for (int ch = 0; ch < HID / BH; ch++) {
        const int hb = ch * BH;

        __syncthreads();

        for (int i = tid; i < BH * C; i += TPB)
            w2s[i] = W2[hb * C + i];

        float acc[8][8];
        #pragma unroll
        for (int i = 0; i < 8; i++)
            #pragma unroll
            for (int j = 0; j < 8; j++) acc[i][j] = 0.0f;

        float4 xr0, xr1, wr0, wr1;

        {
            int kb = 0;
            int f = tid;       { int r = f >> 2, k4 = f & 3; int gr = row0 + r;
                xr0 = (gr < N) ? *(const float4*)(x + (size_t)gr * FIN + kb + k4 * 4)
                               : make_float4(0.f, 0.f, 0.f, 0.f); }
            f = TPB + tid;     { int r = f >> 2, k4 = f & 3; int gr = row0 + r;
                xr1 = (gr < N) ? *(const float4*)(x + (size_t)gr * FIN + kb + k4 * 4)
                               : make_float4(0.f, 0.f, 0.f, 0.f); }
            f = tid;           { int k = f >> 5, c4 = f & 31;
                wr0 = *(const float4*)(W1 + (size_t)(kb + k) * HID + hb + c4 * 4); }
            f = TPB + tid;     { int k = f >> 5, c4 = f & 31;
                wr1 = *(const float4*)(W1 + (size_t)(kb + k) * HID + hb + c4 * 4); }
        }

        for (int kt = 0; kt < FIN / BK; kt++) {
            __syncthreads();

            {
                int f = tid;     int r = f >> 2, k4 = f & 3;
                xs[(k4 * 4 + 0) * XS_STRIDE + r] = xr0.x;
                xs[(k4 * 4 + 1) * XS_STRIDE + r] = xr0.y;
                xs[(k4 * 4 + 2) * XS_STRIDE + r] = xr0.z;
                xs[(k4 * 4 + 3) * XS_STRIDE + r] = xr0.w;
                f = TPB + tid;   r = f >> 2; k4 = f & 3;
                xs[(k4 * 4 + 0) * XS_STRIDE + r] = xr1.x;
                xs[(k4 * 4 + 1) * XS_STRIDE + r] = xr1.y;
                xs[(k4 * 4 + 2) * XS_STRIDE + r] = xr1.z;
                xs[(k4 * 4 + 3) * XS_STRIDE + r] = xr1.w;
                f = tid;        *(float4*)&wsm[(f >> 5) * BH + (f & 31) * 4] = wr0;
                f = TPB + tid;  *(float4*)&wsm[(f >> 5) * BH + (f & 31) * 4] = wr1;
            }
            __syncthreads();

            if (kt + 1 < FIN / BK) {
                int kb = (kt + 1) * BK;
                int f = tid;       { int r = f >> 2, k4 = f & 3; int gr = row0 + r;
                    xr0 = (gr < N) ? *(const float4*)(x + (size_t)gr * FIN + kb + k4 * 4)
                                   : make_float4(0.f, 0.f, 0.f, 0.f); }
                f = TPB + tid;     { int r = f >> 2, k4 = f & 3; int gr = row0 + r;
                    xr1 = (gr < N) ? *(const float4*)(x + (size_t)gr * FIN + kb + k4 * 4)
                                   : make_float4(0.f, 0.f, 0.f, 0.f); }
                f = tid;           { int k = f >> 5, c4 = f & 31;
                    wr0 = *(const float4*)(W1 + (size_t)(kb + k) * HID + hb + c4 * 4); }
                f = TPB + tid;     { int k = f >> 5, c4 = f & 31;
                    wr1 = *(const float4*)(W1 + (size_t)(kb + k) * HID + hb + c4 * 4); }
            }

            #pragma unroll
            for (int k = 0; k < BK; k++) {
                float a[8], b[8];
                *(float4*)&a[0] = *(const float4*)&xs[k * XS_STRIDE + ty * 8];
                *(float4*)&a[4] = *(const float4*)&xs[k * XS_STRIDE + ty * 8 + 4];
                *(float4*)&b[0] = *(const float4*)&wsm[k * BH + tx * 8];
                *(float4*)&b[4] = *(const float4*)&wsm[k * BH + tx * 8 + 4];
                #pragma unroll
                for (int i = 0; i < 8; i++)
                    #pragma unroll
                    for (int j = 0; j < 8; j++)
                        acc[i][j] = fmaf(a[i], b[j], acc[i][j]);
            }
        }

        float bv[8];
        #pragma unroll
        for (int j = 0; j < 8; j++) bv[j] = b1[hb + tx * 8 + j];
        #pragma unroll
        for (int i = 0; i < 8; i++)
            #pragma unroll
            for (int j = 0; j < 8; j++)
                hs[(ty * 8 + i) * HS_STRIDE + tx * 8 + j] =
                    fmaxf(acc[i][j] + bv[j], 0.0f);
        __syncthreads();

        #pragma unroll 4
        for (int k = 0; k < BH; k++) {
            float h0 = hs[(rb + 0) * HS_STRIDE + k];
            float h1 = hs[(rb + 1) * HS_STRIDE + k];
            float h2 = hs[(rb + 2) * HS_STRIDE + k];
            float h3 = hs[(rb + 3) * HS_STRIDE + k];
            #pragma unroll
            for (int c = 0; c < 5; c++) {
                float wv = w2s[k * C + cb + c];
                zacc[0][c] = fmaf(h0, wv, zacc[0][c]);
                zacc[1][c] = fmaf(h1, wv, zacc[1][c]);
                zacc[2][c] = fmaf(h2, wv, zacc[2][c]);
                zacc[3][c] = fmaf(h3, wv, zacc[3][c]);
            }
        }
    }

    float b2v[5];
    #pragma unroll
    for (int c = 0; c < 5; c++) b2v[c] = b2[cb + c];
    #pragma unroll
    for (int i = 0; i < 4; i++) {
        int r = row0 + rb + i;
        if (r < N) {
            #pragma unroll
            for (int c = 0; c < 5; c++)
                z0[(size_t)r * C + cb + c] = zacc[i][c] + b2v[c];
        }
    }
}

// ---------------- APPNP iteration: pure CSR gather --------------------------
// out[r] = ALPHA*z0[r] + 0.9*dinv[r]^2*zp[r] + sum_{e in CSR(r)} w_e * zp[col_e]
// One thread per (node, float4 chunk): N*10 threads.
__global__ void __launch_bounds__(256)
k_prop(const float* __restrict__ zp, float* __restrict__ out) {
    unsigned t = blockIdx.x * blockDim.x + threadIdx.x;
    if (t >= (unsigned)N * 10u) return;
    unsigned r = t / 10u;
    unsigned c = t - r * 10u;          // chunk 0..9 -> floats [4c,4c+4)

    const size_t off = (size_t)r * C + c * 4;
    float d = g_dinv[r];
    float s = (1.0f - ALPHA) * d * d;

    float4 z0v = *(const float4*)(g_Z0 + off);
    float4 zpv = *(const float4*)(zp + off);
    float4 acc;
    acc.x = fmaf(s, zpv.x, ALPHA * z0v.x);
    acc.y = fmaf(s, zpv.y, ALPHA * z0v.y);
    acc.z = fmaf(s, zpv.z, ALPHA * z0v.z);
    acc.w = fmaf(s, zpv.w, ALPHA * z0v.w);

    int beg = g_base[r];
    int end = beg + (g_deg[r] - 1);

    int e = beg;
    // 2-wide software pipeline to expose MLP
    for (; e + 1 < end; e += 2) {
        int2 m0 = g_meta[e];
        int2 m1 = g_meta[e + 1];
        float w0 = __int_as_float(m0.y);
        float w1 = __int_as_float(m1.y);
        float4 v0 = *(const float4*)(zp + (size_t)m0.x * C + c * 4);
        float4 v1 = *(const float4*)(zp + (size_t)m1.x * C + c * 4);
        acc.x = fmaf(w0, v0.x, acc.x); acc.y = fmaf(w0, v0.y, acc.y);
        acc.z = fmaf(w0, v0.z, acc.z); acc.w = fmaf(w0, v0.w, acc.w);
        acc.x = fmaf(w1, v1.x, acc.x); acc.y = fmaf(w1, v1.y, acc.y);
        acc.z = fmaf(w1, v1.z, acc.z); acc.w = fmaf(w1, v1.w, acc.w);
    }
    if (e < end) {
        int2 m = g_meta[e];
        float w = __int_as_float(m.y);
        float4 v = *(const float4*)(zp + (size_t)m.x * C + c * 4);
        acc.x = fmaf(w, v.x, acc.x); acc.y = fmaf(w, v.y, acc.y);
        acc.z = fmaf(w, v.z, acc.z); acc.w = fmaf(w, v.w, acc.w);
    }

    *(float4*)(out + off) = acc;
}

// ---------------- launch ----------------------------------------------------
extern "C" void kernel_launch(void* const* d_in, const int* in_sizes, int n_in,
                              void* d_out, int out_size) {
    const float* x  = (const float*)d_in[0];
    const float* W1 = (const float*)d_in[1];
    const float* b1 = (const float*)d_in[2];
    const float* W2 = (const float*)d_in[3];
    const float* b2 = (const float*)d_in[4];
    const int*   ei = (const int*)  d_in[5];
    float* out = (float*)d_out;

    float *Z0, *ZA, *ZB;
    cudaGetSymbolAddress((void**)&Z0, g_Z0);
    cudaGetSymbolAddress((void**)&ZA, g_ZA);
    cudaGetSymbolAddress((void**)&ZB, g_ZB);

    // setup (5 launches so k_gemm is launch index 5 for the -s 5 ncu capture)
    k_reset    <<<(N + 255) / 256, 256>>>();
    k_deg_count<<<(EDG + 255) / 256, 256>>>(ei);
    k_dinv_base<<<(N + 255) / 256, 256>>>();
    k_cursor   <<<(N + 255) / 256, 256>>>();
    k_scatter  <<<(EDG + 255) / 256, 256>>>(ei);

    // fused MLP
    cudaFuncSetAttribute(k_gemm, cudaFuncAttributeMaxDynamicSharedMemorySize,
                         GEMM_SMEM_BYTES);
    k_gemm<<<(N + BM - 1) / BM, TPB, GEMM_SMEM_BYTES>>>(x, W1, b1, W2, b2, Z0);

    // APPNP: pure gather per iteration; last iteration writes d_out
    const float* zp = Z0;
    for (int it = 1; it <= KITER; it++) {
        float* tgt = (it == KITER) ? out : ((it & 1) ? ZA : ZB);
        k_prop<<<((unsigned)N * 10u + 255) / 256, 256>>>(zp, tgt);
        zp = tgt;
    }
}

// round 4
// speedup vs baseline: 1.8417x; 1.6061x over previous
#include <cuda_runtime.h>
#include <cuda_bf16.h>
#include <cstdint>

#define N        100000
#define NPAD     100096
#define FIN      512
#define HID      512
#define C        40
#define EDG      1600000
#define KITER    10
#define ALPHA    0.1f

// ---------------- scratch (device globals; no allocation allowed) ----------
__device__ float g_Z0[(size_t)N * C];
__device__ float g_ZA[(size_t)N * C];
__device__ float g_ZB[(size_t)N * C];
__device__ float g_dinv[N];
__device__ int   g_deg[N];
__device__ int   g_base[N];
__device__ int   g_cursor[N];
__device__ int2  g_meta[EDG];
__device__ int   g_total;

__device__ __nv_bfloat16 g_xhi[(size_t)NPAD * FIN];   // rows >= N stay zero
__device__ __nv_bfloat16 g_xlo[(size_t)NPAD * FIN];
__device__ __nv_bfloat16 g_w1hi[(size_t)HID * FIN];   // transposed: [n][k]
__device__ __nv_bfloat16 g_w1lo[(size_t)HID * FIN];

// ---------------- PTX helpers ----------------------------------------------
__device__ __forceinline__ uint32_t smem_u32(const void* p) {
    uint32_t a;
    asm("{ .reg .u64 t; cvta.to.shared.u64 t, %1; cvt.u32.u64 %0, t; }"
        : "=r"(a) : "l"(p));
    return a;
}
__device__ __forceinline__ void cp16(uint32_t s, const void* g) {
    asm volatile("cp.async.cg.shared.global [%0], [%1], 16;"
                 :: "r"(s), "l"(g));
}
#define CP_COMMIT()  asm volatile("cp.async.commit_group;" ::: "memory")
#define CP_WAIT(n)   asm volatile("cp.async.wait_group %0;" :: "n"(n) : "memory")

#define LDSM4(r, a) \
    asm volatile("ldmatrix.sync.aligned.m8n8.x4.shared.b16 {%0,%1,%2,%3}, [%4];" \
        : "=r"((r)[0]), "=r"((r)[1]), "=r"((r)[2]), "=r"((r)[3]) : "r"(a))

#define MMA_BF16(d, a, b0, b1) \
    asm volatile("mma.sync.aligned.m16n8k16.row.col.f32.bf16.bf16.f32 " \
        "{%0,%1,%2,%3}, {%4,%5,%6,%7}, {%8,%9}, {%0,%1,%2,%3};" \
        : "+f"((d)[0]), "+f"((d)[1]), "+f"((d)[2]), "+f"((d)[3]) \
        : "r"((a)[0]), "r"((a)[1]), "r"((a)[2]), "r"((a)[3]), "r"(b0), "r"(b1))

// ---------------- setup -----------------------------------------------------
__global__ void k_reset() {
    int i = blockIdx.x * blockDim.x + threadIdx.x;
    if (i < N) g_deg[i] = 1;
    if (i == 0) g_total = 0;
}
__global__ void k_deg_count(const int* __restrict__ ei) {
    int e = blockIdx.x * blockDim.x + threadIdx.x;
    if (e < EDG) atomicAdd(&g_deg[ei[e]], 1);
}
__global__ void k_dinv_base() {
    int i = blockIdx.x * blockDim.x + threadIdx.x;
    if (i < N) {
        int d = g_deg[i];
        g_dinv[i] = rsqrtf((float)d);
        g_base[i] = atomicAdd(&g_total, d - 1);
    }
}
__global__ void k_cursor() {
    int i = blockIdx.x * blockDim.x + threadIdx.x;
    if (i < N) g_cursor[i] = g_base[i];
}
__global__ void k_scatter(const int* __restrict__ ei) {
    int e = blockIdx.x * blockDim.x + threadIdx.x;
    if (e < EDG) {
        int r = ei[e];
        int s = ei[EDG + e];
        float w = (1.0f - ALPHA) * g_dinv[r] * g_dinv[s];
        int pos = atomicAdd(&g_cursor[r], 1);
        g_meta[pos] = make_int2(s, __float_as_int(w));
    }
}

// ---------------- conversions ----------------------------------------------
__global__ void k_cvt_x(const float* __restrict__ x) {
    size_t i = (size_t)blockIdx.x * blockDim.x + threadIdx.x;
    if (i >= (size_t)N * FIN / 8) return;
    float4 a = ((const float4*)x)[i * 2];
    float4 b = ((const float4*)x)[i * 2 + 1];
    float v[8] = {a.x, a.y, a.z, a.w, b.x, b.y, b.z, b.w};
    __nv_bfloat16 hi[8], lo[8];
    #pragma unroll
    for (int j = 0; j < 8; j++) {
        hi[j] = __float2bfloat16_rn(v[j]);
        lo[j] = __float2bfloat16_rn(v[j] - __bfloat162float(hi[j]));
    }
    ((uint4*)g_xhi)[i] = *(uint4*)hi;
    ((uint4*)g_xlo)[i] = *(uint4*)lo;
}

__global__ void k_cvt_w1(const float* __restrict__ W1) {
    __shared__ float t[32][33];
    int bx = blockIdx.x & 15, by = blockIdx.x >> 4;
    int tx = threadIdx.x & 31, ty = threadIdx.x >> 5;
    t[ty][tx] = W1[(size_t)(by * 32 + ty) * HID + bx * 32 + tx];
    __syncthreads();
    int n = bx * 32 + ty, k = by * 32 + tx;
    float v = t[tx][ty];
    __nv_bfloat16 hi = __float2bfloat16_rn(v);
    __nv_bfloat16 lo = __float2bfloat16_rn(v - __bfloat162float(hi));
    g_w1hi[(size_t)n * FIN + k] = hi;
    g_w1lo[(size_t)n * FIN + k] = lo;
}

__global__ void k_z0init(const float* __restrict__ b2) {
    unsigned t = blockIdx.x * blockDim.x + threadIdx.x;
    if (t >= (unsigned)N * 10u) return;
    unsigned c = t % 10u;
    ((float4*)g_Z0)[t] = ((const float4*)b2)[c];
}

// ---------------- bf16-split mma.sync GEMM + fused epilogue -----------------
// CTA tile 128(M) x 128(N hidden), K=512, BK=32, 3-stage cp.async.
// u = xh*wh + xh*wl + xl*wh; epilogue: h=relu(u+b1); red.add h@W2 into g_Z0.
#define BK      32
#define SA      40                        // bf16 row stride (80 B)
#define MATB    (128 * SA * 2)            // 10240 B per matrix
#define STGB    (4 * MATB)                // stage: Ahi|Alo|Bhi|Blo
#define OFF_ALO MATB
#define OFF_BHI (2 * MATB)
#define OFF_BLO (3 * MATB)
#define NSTG    3
#define GEMM_SMEM (NSTG * STGB)           // 122880
#define HSS     136
#define EPI_W2  (128 * HSS * 4)           // 69632
#define EPI_B1  (EPI_W2 + 128 * C * 4)    // 90112

__device__ __forceinline__ void prefetch(uint32_t sb, int stage, int m0, int n0,
                                         int kc, int tid) {
    uint32_t st = sb + stage * STGB;
    int r = tid >> 2, seg = tid & 3;
    const __nv_bfloat16* xh = g_xhi  + (size_t)(m0 + r) * FIN + kc * BK + seg * 8;
    const __nv_bfloat16* xl = g_xlo  + (size_t)(m0 + r) * FIN + kc * BK + seg * 8;
    const __nv_bfloat16* wh = g_w1hi + (size_t)(n0 + r) * FIN + kc * BK + seg * 8;
    const __nv_bfloat16* wl = g_w1lo + (size_t)(n0 + r) * FIN + kc * BK + seg * 8;
    uint32_t d = st + r * (SA * 2) + seg * 16;
    uint32_t d2 = d + 64 * (SA * 2);
    size_t rof = (size_t)64 * FIN;
    cp16(d,            xh);        cp16(d2,            xh + rof);
    cp16(d + OFF_ALO,  xl);        cp16(d2 + OFF_ALO,  xl + rof);
    cp16(d + OFF_BHI,  wh);        cp16(d2 + OFF_BHI,  wh + rof);
    cp16(d + OFF_BLO,  wl);        cp16(d2 + OFF_BLO,  wl + rof);
}

__global__ void __launch_bounds__(256, 1)
k_mma(const float* __restrict__ W2, const float* __restrict__ b1) {
    extern __shared__ char smem[];
    uint32_t sb = smem_u32(smem);
    const int tid = threadIdx.x, lane = tid & 31, wid = tid >> 5;
    const int m0 = (blockIdx.x >> 2) * 128;
    const int n0 = (blockIdx.x & 3) * 128;
    const int wm = (wid >> 1) * 32;      // warp M offset
    const int wn = (wid & 1) * 64;       // warp N offset

    float acc[2][8][4];
    #pragma unroll
    for (int t = 0; t < 2; t++)
        #pragma unroll
        for (int nt = 0; nt < 8; nt++)
            #pragma unroll
            for (int q = 0; q < 4; q++) acc[t][nt][q] = 0.0f;

    prefetch(sb, 0, m0, n0, 0, tid); CP_COMMIT();
    prefetch(sb, 1, m0, n0, 1, tid); CP_COMMIT();

    // ldmatrix lane addressing (constant per thread)
    const int arow = (lane & 15);
    const int acolB = (lane >> 4) * 8;
    const int brow = (lane & 7) + ((lane >> 4) << 3);
    const int bcolB = ((lane >> 3) & 1) * 8;

    #pragma unroll 1
    for (int kc = 0; kc < FIN / BK; kc++) {
        if (kc >= FIN / BK - 2) CP_WAIT(0); else CP_WAIT(1);
        __syncthreads();
        if (kc + 2 < FIN / BK) {
            prefetch(sb, (kc + 2) % NSTG, m0, n0, kc + 2, tid);
            CP_COMMIT();
        }
        uint32_t st = sb + (kc % NSTG) * STGB;

        #pragma unroll
        for (int s = 0; s < 2; s++) {
            uint32_t ahi[2][4], alo[2][4], bhi[4][4], blo[4][4];
            #pragma unroll
            for (int t = 0; t < 2; t++) {
                uint32_t ad = st + ((wm + t * 16 + arow) * SA + s * 16 + acolB) * 2;
                LDSM4(ahi[t], ad);
                LDSM4(alo[t], ad + OFF_ALO);
            }
            #pragma unroll
            for (int g = 0; g < 4; g++) {
                uint32_t bd = st + OFF_BHI +
                              ((wn + g * 16 + brow) * SA + s * 16 + bcolB) * 2;
                LDSM4(bhi[g], bd);
                LDSM4(blo[g], bd + MATB);
            }
            #pragma unroll
            for (int t = 0; t < 2; t++)
                #pragma unroll
                for (int g = 0; g < 4; g++)
                    #pragma unroll
                    for (int h2 = 0; h2 < 2; h2++) {
                        int nt = g * 2 + h2;
                        MMA_BF16(acc[t][nt], ahi[t], bhi[g][h2 * 2], bhi[g][h2 * 2 + 1]);
                        MMA_BF16(acc[t][nt], ahi[t], blo[g][h2 * 2], blo[g][h2 * 2 + 1]);
                        MMA_BF16(acc[t][nt], alo[t], bhi[g][h2 * 2], bhi[g][h2 * 2 + 1]);
                    }
        }
    }

    // ---- epilogue: overlay smem ----
    __syncthreads();
    float* hs  = (float*)smem;                 // [128][HSS]
    float* w2s = (float*)(smem + EPI_W2);      // [128][C]
    float* b1s = (float*)(smem + EPI_B1);      // [128]
    for (int i = tid; i < 128 * C; i += 256) w2s[i] = W2[(size_t)n0 * C + i];
    if (tid < 128) b1s[tid] = b1[n0 + tid];
    __syncthreads();

    const int r0 = wm + (lane >> 2);
    const int cb0 = wn + (lane & 3) * 2;
    #pragma unroll
    for (int t = 0; t < 2; t++)
        #pragma unroll
        for (int nt = 0; nt < 8; nt++) {
            int rr = r0 + t * 16, cc = cb0 + nt * 8;
            hs[rr * HSS + cc]           = fmaxf(acc[t][nt][0] + b1s[cc], 0.0f);
            hs[rr * HSS + cc + 1]       = fmaxf(acc[t][nt][1] + b1s[cc + 1], 0.0f);
            hs[(rr + 8) * HSS + cc]     = fmaxf(acc[t][nt][2] + b1s[cc], 0.0f);
            hs[(rr + 8) * HSS + cc + 1] = fmaxf(acc[t][nt][3] + b1s[cc + 1], 0.0f);
        }
    __syncthreads();

    // mini-gemm: z[128,40] += hs[128,128] @ w2s[128,40]
    const int rb = (tid >> 3) * 4;
    const int cb = (tid & 7) * 5;
    float z[4][5];
    #pragma unroll
    for (int i = 0; i < 4; i++)
        #pragma unroll
        for (int c = 0; c < 5; c++) z[i][c] = 0.0f;
    #pragma unroll 4
    for (int k = 0; k < 128; k++) {
        float h0 = hs[(rb + 0) * HSS + k];
        float h1 = hs[(rb + 1) * HSS + k];
        float h2 = hs[(rb + 2) * HSS + k];
        float h3 = hs[(rb + 3) * HSS + k];
        #pragma unroll
        for (int c = 0; c < 5; c++) {
            float wv = w2s[k * C + cb + c];
            z[0][c] = fmaf(h0, wv, z[0][c]);
            z[1][c] = fmaf(h1, wv, z[1][c]);
            z[2][c] = fmaf(h2, wv, z[2][c]);
            z[3][c] = fmaf(h3, wv, z[3][c]);
        }
    }
    #pragma unroll
    for (int i = 0; i < 4; i++) {
        int gr = m0 + rb + i;
        if (gr < N) {
            float* dst = g_Z0 + (size_t)gr * C + cb;
            #pragma unroll
            for (int c = 0; c < 5; c++)
                asm volatile("red.global.add.f32 [%0], %1;"
                             :: "l"(dst + c), "f"(z[i][c]) : "memory");
        }
    }
}

// ---------------- APPNP: warp-per-node CSR gather ---------------------------
__global__ void __launch_bounds__(256)
k_prop(const float* __restrict__ zp, float* __restrict__ out) {
    int w = (blockIdx.x * blockDim.x + threadIdx.x) >> 5;
    if (w >= N) return;
    const int lane = threadIdx.x & 31;
    const size_t ro = (size_t)w * C;

    float d = g_dinv[w];
    float s = (1.0f - ALPHA) * d * d;
    float a0 = fmaf(s, zp[ro + lane], ALPHA * g_Z0[ro + lane]);
    float a1 = 0.0f;
    if (lane < 8) a1 = fmaf(s, zp[ro + 32 + lane], ALPHA * g_Z0[ro + 32 + lane]);

    int beg = g_base[w];
    int cnt = g_deg[w] - 1;

    if (cnt > 0) {
        int2 m = g_meta[beg];                       // uniform broadcast load
        for (int j = 0; j < cnt; j++) {
            int2 mn = (j + 1 < cnt) ? g_meta[beg + j + 1] : m;  // pipeline
            float wgt = __int_as_float(m.y);
            const float* zr = zp + (size_t)m.x * C;
            a0 = fmaf(wgt, zr[lane], a0);
            if (lane < 8) a1 = fmaf(wgt, zr[32 + lane], a1);
            m = mn;
        }
    }
    out[ro + lane] = a0;
    if (lane < 8) out[ro + 32 + lane] = a1;
}

// ---------------- launch ----------------------------------------------------
extern "C" void kernel_launch(void* const* d_in, const int* in_sizes, int n_in,
                              void* d_out, int out_size) {
    const float* x  = (const float*)d_in[0];
    const float* W1 = (const float*)d_in[1];
    const float* b1 = (const float*)d_in[2];
    const float* W2 = (const float*)d_in[3];
    const float* b2 = (const float*)d_in[4];
    const int*   ei = (const int*)  d_in[5];
    float* out = (float*)d_out;

    float *Z0, *ZA, *ZB;
    cudaGetSymbolAddress((void**)&Z0, g_Z0);
    cudaGetSymbolAddress((void**)&ZA, g_ZA);
    cudaGetSymbolAddress((void**)&ZB, g_ZB);

    // order chosen so k_mma is launch index 5 (ncu -s 5 -c 1)
    k_cvt_x   <<<((size_t)N * FIN / 8 + 255) / 256, 256>>>(x);     // 0
    k_cvt_w1  <<<256, 1024>>>(W1);                                  // 1
    k_z0init  <<<(N * 10 + 255) / 256, 256>>>(b2);                  // 2
    k_reset   <<<(N + 255) / 256, 256>>>();                         // 3
    k_deg_count<<<(EDG + 255) / 256, 256>>>(ei);                    // 4

    cudaFuncSetAttribute(k_mma, cudaFuncAttributeMaxDynamicSharedMemorySize,
                         GEMM_SMEM);
    k_mma<<<(NPAD / 128) * 4, 256, GEMM_SMEM>>>(W2, b1);            // 5

    k_dinv_base<<<(N + 255) / 256, 256>>>();                        // 6
    k_cursor   <<<(N + 255) / 256, 256>>>();                        // 7
    k_scatter  <<<(EDG + 255) / 256, 256>>>(ei);                    // 8

    const float* zp = Z0;
    for (int it = 1; it <= KITER; it++) {
        float* tgt = (it == KITER) ? out : ((it & 1) ? ZA : ZB);
        k_prop<<<(N * 32 + 255) / 256, 256>>>(zp, tgt);
        zp = tgt;
    }
}

// round 5
// speedup vs baseline: 3.0206x; 1.6401x over previous
#include <cuda_runtime.h>
#include <cstdint>

#define N        100000
#define NPAD     100096
#define FIN      512
#define HID      512
#define C        40
#define EDG      1600000
#define KITER    10
#define ALPHA    0.1f

// ---------------- scratch (device globals; no allocation allowed) ----------
__device__ float g_Z0[(size_t)N * C];
__device__ float g_ZA[(size_t)N * C];
__device__ float g_ZB[(size_t)N * C];
__device__ float g_dinv[N];
__device__ int   g_deg[N];
__device__ int   g_base[N];
__device__ int   g_cursor[N];
__device__ int2  g_meta[EDG];
__device__ int   g_total;
__device__ float g_w1t[(size_t)HID * FIN];   // W1^T [n][k], tf32-rounded

// ---------------- PTX helpers ----------------------------------------------
__device__ __forceinline__ uint32_t smem_u32(const void* p) {
    uint32_t a;
    asm("{ .reg .u64 t; cvta.to.shared.u64 t, %1; cvt.u32.u64 %0, t; }"
        : "=r"(a) : "l"(p));
    return a;
}
__device__ __forceinline__ void cp16(uint32_t s, const void* g) {
    asm volatile("cp.async.cg.shared.global [%0], [%1], 16;" :: "r"(s), "l"(g));
}
__device__ __forceinline__ void cp16p(uint32_t s, const void* g, int bytes) {
    asm volatile("cp.async.cg.shared.global [%0], [%1], 16, %2;"
                 :: "r"(s), "l"(g), "r"(bytes));
}
#define CP_COMMIT()  asm volatile("cp.async.commit_group;" ::: "memory")
#define CP_WAIT(n)   asm volatile("cp.async.wait_group %0;" :: "n"(n) : "memory")

__device__ __forceinline__ uint32_t to_tf32(float f) {
    uint32_t u;
    asm("cvt.rna.tf32.f32 %0, %1;" : "=r"(u) : "f"(f));
    return u;
}

#define MMA_TF32(d, a, b0, b1) \
    asm volatile("mma.sync.aligned.m16n8k8.row.col.f32.tf32.tf32.f32 " \
        "{%0,%1,%2,%3}, {%4,%5,%6,%7}, {%8,%9}, {%0,%1,%2,%3};" \
        : "+f"((d)[0]), "+f"((d)[1]), "+f"((d)[2]), "+f"((d)[3]) \
        : "r"((a)[0]), "r"((a)[1]), "r"((a)[2]), "r"((a)[3]), "r"(b0), "r"(b1))

// ---------------- setup -----------------------------------------------------
__global__ void k_reset() {
    int i = blockIdx.x * blockDim.x + threadIdx.x;
    if (i < N) g_deg[i] = 1;
    if (i == 0) g_total = 0;
}
__global__ void k_deg_count(const int* __restrict__ ei) {
    int e = blockIdx.x * blockDim.x + threadIdx.x;
    if (e < EDG) atomicAdd(&g_deg[ei[e]], 1);
}
__global__ void k_dinv_base() {
    int i = blockIdx.x * blockDim.x + threadIdx.x;
    if (i < N) {
        int d = g_deg[i];
        g_dinv[i] = rsqrtf((float)d);
        g_base[i] = atomicAdd(&g_total, d - 1);
    }
}
__global__ void k_cursor() {
    int i = blockIdx.x * blockDim.x + threadIdx.x;
    if (i < N) g_cursor[i] = g_base[i];
}
__global__ void k_scatter(const int* __restrict__ ei) {
    int e = blockIdx.x * blockDim.x + threadIdx.x;
    if (e < EDG) {
        int r = ei[e];
        int s = ei[EDG + e];
        float w = (1.0f - ALPHA) * g_dinv[r] * g_dinv[s];
        int pos = atomicAdd(&g_cursor[r], 1);
        g_meta[pos] = make_int2(s, __float_as_int(w));
    }
}

// W1 [k][n] -> g_w1t [n][k], tf32-rounded
__global__ void k_cvt_w1(const float* __restrict__ W1) {
    __shared__ float t[32][33];
    int bx = blockIdx.x & 15, by = blockIdx.x >> 4;
    int tx = threadIdx.x & 31, ty = threadIdx.x >> 5;
    t[ty][tx] = W1[(size_t)(by * 32 + ty) * HID + bx * 32 + tx];
    __syncthreads();
    int n = bx * 32 + ty, k = by * 32 + tx;
    g_w1t[(size_t)n * FIN + k] = __uint_as_float(to_tf32(t[tx][ty]));
}

__global__ void k_z0init(const float* __restrict__ b2) {
    unsigned t = blockIdx.x * blockDim.x + threadIdx.x;
    if (t >= (unsigned)N * 10u) return;
    unsigned c = t % 10u;
    ((float4*)g_Z0)[t] = ((const float4*)b2)[c];
}

// ---------------- TF32 GEMM1 + tensor-core GEMM2 epilogue -------------------
// CTA tile 128(M) x 128(N hidden), K=512, BK=32 fp32, 4-stage cp.async.
#define BK      32
#define SA      36                        // fp32 row stride
#define MATB    (128 * SA * 4)            // 18432 B
#define STGB    (2 * MATB)                // A | B per stage
#define NSTG    4
#define GEMM_SMEM (NSTG * STGB)           // 147456
#define HSS     132
#define EPI_W2  (128 * HSS * 4)           // 67584
#define EPI_B1  (EPI_W2 + 128 * C * 4)    // 88064

__device__ __forceinline__ void prefetch(uint32_t sb, int stage,
                                         const float* __restrict__ x,
                                         int m0, int n0, int kc, int tid) {
    uint32_t st = sb + stage * STGB;
    #pragma unroll
    for (int i = 0; i < 4; i++) {
        int idx = tid + i * 256;          // 1024 chunks per matrix
        int row = idx >> 3, seg = idx & 7;
        uint32_t d = st + (row * SA + seg * 4) * 4;
        int ab = (m0 + row < N) ? 16 : 0;
        cp16p(d, x + (size_t)(m0 + row) * FIN + kc * BK + seg * 4, ab);
        cp16(d + MATB, g_w1t + (size_t)(n0 + row) * FIN + kc * BK + seg * 4);
    }
}

__global__ void __launch_bounds__(256, 1)
k_mma(const float* __restrict__ x, const float* __restrict__ W2,
      const float* __restrict__ b1) {
    extern __shared__ char smem[];
    uint32_t sb = smem_u32(smem);
    const int tid = threadIdx.x, lane = tid & 31, wid = tid >> 5;
    const int m0 = (blockIdx.x >> 2) * 128;
    const int n0 = (blockIdx.x & 3) * 128;
    const int wm = (wid >> 1) * 32;       // warp M offset (2 mtiles)
    const int wn = (wid & 1) * 64;        // warp N offset (8 ntiles)
    const int gq = lane >> 2, t4 = lane & 3;

    float acc[2][8][4];
    #pragma unroll
    for (int t = 0; t < 2; t++)
        #pragma unroll
        for (int nt = 0; nt < 8; nt++)
            #pragma unroll
            for (int q = 0; q < 4; q++) acc[t][nt][q] = 0.0f;

    prefetch(sb, 0, x, m0, n0, 0, tid); CP_COMMIT();
    prefetch(sb, 1, x, m0, n0, 1, tid); CP_COMMIT();
    prefetch(sb, 2, x, m0, n0, 2, tid); CP_COMMIT();

    #pragma unroll 1
    for (int kc = 0; kc < FIN / BK; kc++) {
        if (kc < 14) CP_WAIT(2);
        else if (kc == 14) CP_WAIT(1);
        else CP_WAIT(0);
        __syncthreads();
        if (kc + 3 < FIN / BK) {
            prefetch(sb, (kc + 3) & 3, x, m0, n0, kc + 3, tid);
            CP_COMMIT();
        }
        const float* As = (const float*)(smem + (kc & 3) * STGB);
        const float* Bs = As + 128 * SA;

        #pragma unroll
        for (int s = 0; s < 4; s++) {
            const int s8 = s * 8;
            uint32_t af[2][4];
            #pragma unroll
            for (int t = 0; t < 2; t++) {
                const float* Ar = As + (wm + t * 16 + gq) * SA + s8 + t4;
                af[t][0] = to_tf32(Ar[0]);
                af[t][1] = to_tf32(Ar[8 * SA]);
                af[t][2] = to_tf32(Ar[4]);
                af[t][3] = to_tf32(Ar[8 * SA + 4]);
            }
            uint32_t bf[8][2];
            #pragma unroll
            for (int nt = 0; nt < 8; nt++) {
                const float* Br = Bs + (wn + nt * 8 + gq) * SA + s8 + t4;
                bf[nt][0] = __float_as_uint(Br[0]);
                bf[nt][1] = __float_as_uint(Br[4]);
            }
            #pragma unroll
            for (int t = 0; t < 2; t++)
                #pragma unroll
                for (int nt = 0; nt < 8; nt++)
                    MMA_TF32(acc[t][nt], af[t], bf[nt][0], bf[nt][1]);
        }
    }

    // ---- epilogue overlay: h = tf32(relu(u + b1)); z = h @ W2slice --------
    __syncthreads();
    float* hs  = (float*)smem;                 // [128][HSS]
    float* w2s = (float*)(smem + EPI_W2);      // [128][C]
    float* b1s = (float*)(smem + EPI_B1);      // [128]
    for (int i = tid; i < 128 * C; i += 256) w2s[i] = W2[(size_t)n0 * C + i];
    if (tid < 128) b1s[tid] = b1[n0 + tid];
    __syncthreads();

    #pragma unroll
    for (int t = 0; t < 2; t++)
        #pragma unroll
        for (int nt = 0; nt < 8; nt++) {
            int r = wm + t * 16 + gq;
            int cc = wn + nt * 8 + 2 * t4;
            float bv0 = b1s[cc], bv1 = b1s[cc + 1];
            float h00 = fmaxf(acc[t][nt][0] + bv0, 0.0f);
            float h01 = fmaxf(acc[t][nt][1] + bv1, 0.0f);
            float h10 = fmaxf(acc[t][nt][2] + bv0, 0.0f);
            float h11 = fmaxf(acc[t][nt][3] + bv1, 0.0f);
            *(float2*)&hs[r * HSS + cc] =
                make_float2(__uint_as_float(to_tf32(h00)), __uint_as_float(to_tf32(h01)));
            *(float2*)&hs[(r + 8) * HSS + cc] =
                make_float2(__uint_as_float(to_tf32(h10)), __uint_as_float(to_tf32(h11)));
        }
    __syncthreads();

    // GEMM2: warp w -> rows [16w, 16w+16), K = 128, 5 ntiles of 8
    float zacc[5][4];
    #pragma unroll
    for (int nt = 0; nt < 5; nt++)
        #pragma unroll
        for (int q = 0; q < 4; q++) zacc[nt][q] = 0.0f;
    const int rw = wid * 16;

    #pragma unroll
    for (int s = 0; s < 16; s++) {
        const float* hr = hs + (rw + gq) * HSS + s * 8 + t4;
        uint32_t af2[4];
        af2[0] = __float_as_uint(hr[0]);
        af2[1] = __float_as_uint(hr[8 * HSS]);
        af2[2] = __float_as_uint(hr[4]);
        af2[3] = __float_as_uint(hr[8 * HSS + 4]);
        #pragma unroll
        for (int nt = 0; nt < 5; nt++) {
            uint32_t b0 = __float_as_uint(w2s[(s * 8 + t4) * C + nt * 8 + gq]);
            uint32_t b1r = __float_as_uint(w2s[(s * 8 + t4 + 4) * C + nt * 8 + gq]);
            MMA_TF32(zacc[nt], af2, b0, b1r);
        }
    }

    int r1 = m0 + rw + gq, r2 = r1 + 8;
    #pragma unroll
    for (int nt = 0; nt < 5; nt++) {
        int col = nt * 8 + 2 * t4;
        if (r1 < N)
            asm volatile("red.global.add.v2.f32 [%0], {%1,%2};"
                :: "l"(g_Z0 + (size_t)r1 * C + col), "f"(zacc[nt][0]), "f"(zacc[nt][1])
                : "memory");
        if (r2 < N)
            asm volatile("red.global.add.v2.f32 [%0], {%1,%2};"
                :: "l"(g_Z0 + (size_t)r2 * C + col), "f"(zacc[nt][2]), "f"(zacc[nt][3])
                : "memory");
    }
}

// ---------------- APPNP: warp-per-node, 3 edges/trip ------------------------
__global__ void __launch_bounds__(256)
k_prop(const float* __restrict__ zp, float* __restrict__ out) {
    int w = (blockIdx.x * blockDim.x + threadIdx.x) >> 5;
    if (w >= N) return;
    const int lane = threadIdx.x & 31;
    const int g = lane / 10;              // 0..2 active groups; 3 = idle lanes
    const int q = lane - g * 10;          // chunk 0..9

    float4 acc = make_float4(0.f, 0.f, 0.f, 0.f);
    const int beg = g_base[w];
    const int cnt = g_deg[w] - 1;

    for (int j = (g < 3) ? g : cnt; j < cnt; j += 3) {
        int2 m = g_meta[beg + j];
        float wgt = __int_as_float(m.y);
        float4 v = *(const float4*)(zp + (size_t)m.x * C + q * 4);
        acc.x = fmaf(wgt, v.x, acc.x);
        acc.y = fmaf(wgt, v.y, acc.y);
        acc.z = fmaf(wgt, v.z, acc.z);
        acc.w = fmaf(wgt, v.w, acc.w);
    }

    // cross-group reduce: lane q (<10) needs lanes q+10, q+20
    float sx1 = __shfl_sync(0xffffffffu, acc.x, lane + 10);
    float sy1 = __shfl_sync(0xffffffffu, acc.y, lane + 10);
    float sz1 = __shfl_sync(0xffffffffu, acc.z, lane + 10);
    float sw1 = __shfl_sync(0xffffffffu, acc.w, lane + 10);
    float sx2 = __shfl_sync(0xffffffffu, acc.x, lane + 20);
    float sy2 = __shfl_sync(0xffffffffu, acc.y, lane + 20);
    float sz2 = __shfl_sync(0xffffffffu, acc.z, lane + 20);
    float sw2 = __shfl_sync(0xffffffffu, acc.w, lane + 20);

    if (g == 0) {
        const size_t off = (size_t)w * C + q * 4;
        float d = g_dinv[w];
        float s = (1.0f - ALPHA) * d * d;
        float4 z0v = *(const float4*)(g_Z0 + off);
        float4 zpv = *(const float4*)(zp + off);
        float4 o;
        o.x = fmaf(s, zpv.x, ALPHA * z0v.x) + acc.x + sx1 + sx2;
        o.y = fmaf(s, zpv.y, ALPHA * z0v.y) + acc.y + sy1 + sy2;
        o.z = fmaf(s, zpv.z, ALPHA * z0v.z) + acc.z + sz1 + sz2;
        o.w = fmaf(s, zpv.w, ALPHA * z0v.w) + acc.w + sw1 + sw2;
        *(float4*)(out + off) = o;
    }
}

// ---------------- launch ----------------------------------------------------
extern "C" void kernel_launch(void* const* d_in, const int* in_sizes, int n_in,
                              void* d_out, int out_size) {
    const float* x  = (const float*)d_in[0];
    const float* W1 = (const float*)d_in[1];
    const float* b1 = (const float*)d_in[2];
    const float* W2 = (const float*)d_in[3];
    const float* b2 = (const float*)d_in[4];
    const int*   ei = (const int*)  d_in[5];
    float* out = (float*)d_out;

    float *Z0, *ZA, *ZB;
    cudaGetSymbolAddress((void**)&Z0, g_Z0);
    cudaGetSymbolAddress((void**)&ZA, g_ZA);
    cudaGetSymbolAddress((void**)&ZB, g_ZB);

    // k_mma at our launch index 3 (ncu -s 5 lands there)
    k_cvt_w1 <<<256, 1024>>>(W1);                                   // 0
    k_z0init <<<(N * 10 + 255) / 256, 256>>>(b2);                   // 1
    k_reset  <<<(N + 255) / 256, 256>>>();                          // 2

    cudaFuncSetAttribute(k_mma, cudaFuncAttributeMaxDynamicSharedMemorySize,
                         GEMM_SMEM);
    k_mma<<<(NPAD / 128) * 4, 256, GEMM_SMEM>>>(x, W2, b1);         // 3

    k_deg_count<<<(EDG + 255) / 256, 256>>>(ei);                    // 4
    k_dinv_base<<<(N + 255) / 256, 256>>>();                        // 5
    k_cursor   <<<(N + 255) / 256, 256>>>();                        // 6
    k_scatter  <<<(EDG + 255) / 256, 256>>>(ei);                    // 7

    const float* zp = Z0;
    for (int it = 1; it <= KITER; it++) {
        float* tgt = (it == KITER) ? out : ((it & 1) ? ZA : ZB);
        k_prop<<<(N * 32 + 255) / 256, 256>>>(zp, tgt);
        zp = tgt;
    }
}

// round 6
// speedup vs baseline: 3.3516x; 1.1096x over previous
#include <cuda_runtime.h>
#include <cstdint>

#define N        100000
#define NPAD     100096
#define FIN      512
#define HID      512
#define C        40
#define EDG      1600000
#define KITER    10
#define ALPHA    0.1f

// ---------------- scratch (device globals; no allocation allowed) ----------
__device__ float g_Z0[(size_t)N * C];
__device__ float g_ZA[(size_t)N * C];
__device__ float g_ZB[(size_t)N * C];
__device__ float g_dinv[N];
__device__ int   g_deg[N];
__device__ int   g_base[N];
__device__ int   g_cursor[N];
__device__ int2  g_meta[EDG];
__device__ int   g_total;
__device__ float g_w1t[(size_t)HID * FIN];   // W1^T [n][k], tf32-rounded

// ---------------- PTX helpers ----------------------------------------------
__device__ __forceinline__ uint32_t smem_u32(const void* p) {
    uint32_t a;
    asm("{ .reg .u64 t; cvta.to.shared.u64 t, %1; cvt.u32.u64 %0, t; }"
        : "=r"(a) : "l"(p));
    return a;
}
__device__ __forceinline__ void cp16(uint32_t s, const void* g) {
    asm volatile("cp.async.cg.shared.global [%0], [%1], 16;" :: "r"(s), "l"(g));
}
__device__ __forceinline__ void cp16p(uint32_t s, const void* g, int bytes) {
    asm volatile("cp.async.cg.shared.global [%0], [%1], 16, %2;"
                 :: "r"(s), "l"(g), "r"(bytes));
}
#define CP_COMMIT()  asm volatile("cp.async.commit_group;" ::: "memory")
#define CP_WAIT(n)   asm volatile("cp.async.wait_group %0;" :: "n"(n) : "memory")

__device__ __forceinline__ uint32_t to_tf32(float f) {
    uint32_t u;
    asm("cvt.rna.tf32.f32 %0, %1;" : "=r"(u) : "f"(f));
    return u;
}

#define MMA_TF32(d, a, b0, b1) \
    asm volatile("mma.sync.aligned.m16n8k8.row.col.f32.tf32.tf32.f32 " \
        "{%0,%1,%2,%3}, {%4,%5,%6,%7}, {%8,%9}, {%0,%1,%2,%3};" \
        : "+f"((d)[0]), "+f"((d)[1]), "+f"((d)[2]), "+f"((d)[3]) \
        : "r"((a)[0]), "r"((a)[1]), "r"((a)[2]), "r"((a)[3]), "r"(b0), "r"(b1))

// ---------------- setup -----------------------------------------------------
__global__ void k_reset() {
    int i = blockIdx.x * blockDim.x + threadIdx.x;
    if (i < N) g_deg[i] = 1;
    if (i == 0) g_total = 0;
}
__global__ void k_deg_count(const int* __restrict__ ei) {
    int e = blockIdx.x * blockDim.x + threadIdx.x;
    if (e < EDG) atomicAdd(&g_deg[ei[e]], 1);
}
__global__ void k_dinv_base() {
    int i = blockIdx.x * blockDim.x + threadIdx.x;
    if (i < N) {
        int d = g_deg[i];
        g_dinv[i] = rsqrtf((float)d);
        g_base[i] = atomicAdd(&g_total, d - 1);
    }
}
__global__ void k_cursor() {
    int i = blockIdx.x * blockDim.x + threadIdx.x;
    if (i < N) g_cursor[i] = g_base[i];
}
__global__ void k_scatter(const int* __restrict__ ei) {
    int e = blockIdx.x * blockDim.x + threadIdx.x;
    if (e < EDG) {
        int r = ei[e];
        int s = ei[EDG + e];
        float w = (1.0f - ALPHA) * g_dinv[r] * g_dinv[s];
        int pos = atomicAdd(&g_cursor[r], 1);
        g_meta[pos] = make_int2(s, __float_as_int(w));
    }
}

// W1 [k][n] -> g_w1t [n][k], tf32-rounded
__global__ void k_cvt_w1(const float* __restrict__ W1) {
    __shared__ float t[32][33];
    int bx = blockIdx.x & 15, by = blockIdx.x >> 4;
    int tx = threadIdx.x & 31, ty = threadIdx.x >> 5;
    t[ty][tx] = W1[(size_t)(by * 32 + ty) * HID + bx * 32 + tx];
    __syncthreads();
    int n = bx * 32 + ty, k = by * 32 + tx;
    g_w1t[(size_t)n * FIN + k] = __uint_as_float(to_tf32(t[tx][ty]));
}

__global__ void k_z0init(const float* __restrict__ b2) {
    unsigned t = blockIdx.x * blockDim.x + threadIdx.x;
    if (t >= (unsigned)N * 10u) return;
    unsigned c = t % 10u;
    ((float4*)g_Z0)[t] = ((const float4*)b2)[c];
}

// ---------------- TF32 GEMM1 + tensor-core GEMM2 epilogue -------------------
// CTA tile 128(M) x 128(N hidden), K=512, BK=32 fp32, 3-stage cp.async,
// 2 CTAs/SM (occupancy was the R5 limiter: tensor=42% @ occ=12%).
#define BK      32
#define SA      36                        // fp32 row stride
#define MATB    (128 * SA * 4)            // 18432 B
#define STGB    (2 * MATB)                // A | B per stage
#define NSTG    3
#define GEMM_SMEM (NSTG * STGB)           // 110592
#define HSS     132
#define EPI_W2  (128 * HSS * 4)           // 67584
#define EPI_B1  (EPI_W2 + 128 * C * 4)    // 88064

__device__ __forceinline__ void prefetch(uint32_t sb, int stage,
                                         const float* __restrict__ x,
                                         int m0, int n0, int kc, int tid) {
    uint32_t st = sb + stage * STGB;
    #pragma unroll
    for (int i = 0; i < 4; i++) {
        int idx = tid + i * 256;          // 1024 chunks per matrix
        int row = idx >> 3, seg = idx & 7;
        uint32_t d = st + (row * SA + seg * 4) * 4;
        int ab = (m0 + row < N) ? 16 : 0;
        cp16p(d, x + (size_t)(m0 + row) * FIN + kc * BK + seg * 4, ab);
        cp16(d + MATB, g_w1t + (size_t)(n0 + row) * FIN + kc * BK + seg * 4);
    }
}

__global__ void __launch_bounds__(256, 2)
k_mma(const float* __restrict__ x, const float* __restrict__ W2,
      const float* __restrict__ b1) {
    extern __shared__ char smem[];
    uint32_t sb = smem_u32(smem);
    const int tid = threadIdx.x, lane = tid & 31, wid = tid >> 5;
    const int m0 = (blockIdx.x >> 2) * 128;
    const int n0 = (blockIdx.x & 3) * 128;
    const int wm = (wid >> 1) * 32;       // warp M offset (2 mtiles)
    const int wn = (wid & 1) * 64;        // warp N offset (8 ntiles)
    const int gq = lane >> 2, t4 = lane & 3;

    float acc[2][8][4];
    #pragma unroll
    for (int t = 0; t < 2; t++)
        #pragma unroll
        for (int nt = 0; nt < 8; nt++)
            #pragma unroll
            for (int q = 0; q < 4; q++) acc[t][nt][q] = 0.0f;

    prefetch(sb, 0, x, m0, n0, 0, tid); CP_COMMIT();
    prefetch(sb, 1, x, m0, n0, 1, tid); CP_COMMIT();

    #pragma unroll 1
    for (int kc = 0; kc < FIN / BK; kc++) {
        if (kc == FIN / BK - 1) CP_WAIT(0); else CP_WAIT(1);
        __syncthreads();
        if (kc + 2 < FIN / BK) {
            prefetch(sb, (kc + 2) % NSTG, x, m0, n0, kc + 2, tid);
            CP_COMMIT();
        }
        const float* As = (const float*)(smem + (kc % NSTG) * STGB);
        const float* Bs = As + 128 * SA;

        #pragma unroll
        for (int s = 0; s < 4; s++) {
            const int s8 = s * 8;
            uint32_t af[2][4];
            #pragma unroll
            for (int t = 0; t < 2; t++) {
                const float* Ar = As + (wm + t * 16 + gq) * SA + s8 + t4;
                af[t][0] = to_tf32(Ar[0]);
                af[t][1] = to_tf32(Ar[8 * SA]);
                af[t][2] = to_tf32(Ar[4]);
                af[t][3] = to_tf32(Ar[8 * SA + 4]);
            }
            uint32_t bf[8][2];
            #pragma unroll
            for (int nt = 0; nt < 8; nt++) {
                const float* Br = Bs + (wn + nt * 8 + gq) * SA + s8 + t4;
                bf[nt][0] = __float_as_uint(Br[0]);
                bf[nt][1] = __float_as_uint(Br[4]);
            }
            #pragma unroll
            for (int t = 0; t < 2; t++)
                #pragma unroll
                for (int nt = 0; nt < 8; nt++)
                    MMA_TF32(acc[t][nt], af[t], bf[nt][0], bf[nt][1]);
        }
    }

    // ---- epilogue overlay: h = tf32(relu(u + b1)); z = h @ W2slice --------
    __syncthreads();
    float* hs  = (float*)smem;                 // [128][HSS]
    float* w2s = (float*)(smem + EPI_W2);      // [128][C]
    float* b1s = (float*)(smem + EPI_B1);      // [128]
    for (int i = tid; i < 128 * C; i += 256) w2s[i] = W2[(size_t)n0 * C + i];
    if (tid < 128) b1s[tid] = b1[n0 + tid];
    __syncthreads();

    #pragma unroll
    for (int t = 0; t < 2; t++)
        #pragma unroll
        for (int nt = 0; nt < 8; nt++) {
            int r = wm + t * 16 + gq;
            int cc = wn + nt * 8 + 2 * t4;
            float bv0 = b1s[cc], bv1 = b1s[cc + 1];
            float h00 = fmaxf(acc[t][nt][0] + bv0, 0.0f);
            float h01 = fmaxf(acc[t][nt][1] + bv1, 0.0f);
            float h10 = fmaxf(acc[t][nt][2] + bv0, 0.0f);
            float h11 = fmaxf(acc[t][nt][3] + bv1, 0.0f);
            *(float2*)&hs[r * HSS + cc] =
                make_float2(__uint_as_float(to_tf32(h00)), __uint_as_float(to_tf32(h01)));
            *(float2*)&hs[(r + 8) * HSS + cc] =
                make_float2(__uint_as_float(to_tf32(h10)), __uint_as_float(to_tf32(h11)));
        }
    __syncthreads();

    // GEMM2: warp w -> rows [16w, 16w+16), K = 128, 5 ntiles of 8
    float zacc[5][4];
    #pragma unroll
    for (int nt = 0; nt < 5; nt++)
        #pragma unroll
        for (int q = 0; q < 4; q++) zacc[nt][q] = 0.0f;
    const int rw = wid * 16;

    #pragma unroll
    for (int s = 0; s < 16; s++) {
        const float* hr = hs + (rw + gq) * HSS + s * 8 + t4;
        uint32_t af2[4];
        af2[0] = __float_as_uint(hr[0]);
        af2[1] = __float_as_uint(hr[8 * HSS]);
        af2[2] = __float_as_uint(hr[4]);
        af2[3] = __float_as_uint(hr[8 * HSS + 4]);
        #pragma unroll
        for (int nt = 0; nt < 5; nt++) {
            uint32_t b0 = __float_as_uint(w2s[(s * 8 + t4) * C + nt * 8 + gq]);
            uint32_t b1r = __float_as_uint(w2s[(s * 8 + t4 + 4) * C + nt * 8 + gq]);
            MMA_TF32(zacc[nt], af2, b0, b1r);
        }
    }

    int r1 = m0 + rw + gq, r2 = r1 + 8;
    #pragma unroll
    for (int nt = 0; nt < 5; nt++) {
        int col = nt * 8 + 2 * t4;
        if (r1 < N)
            asm volatile("red.global.add.v2.f32 [%0], {%1,%2};"
                :: "l"(g_Z0 + (size_t)r1 * C + col), "f"(zacc[nt][0]), "f"(zacc[nt][1])
                : "memory");
        if (r2 < N)
            asm volatile("red.global.add.v2.f32 [%0], {%1,%2};"
                :: "l"(g_Z0 + (size_t)r2 * C + col), "f"(zacc[nt][2]), "f"(zacc[nt][3])
                : "memory");
    }
}

// ---------------- APPNP: warp-per-node, 3 edges/trip ------------------------
__global__ void __launch_bounds__(256)
k_prop(const float* __restrict__ zp, float* __restrict__ out) {
    int w = (blockIdx.x * blockDim.x + threadIdx.x) >> 5;
    if (w >= N) return;
    const int lane = threadIdx.x & 31;
    const int g = lane / 10;              // 0..2 active groups; 3 = idle lanes
    const int q = lane - g * 10;          // chunk 0..9

    float4 acc = make_float4(0.f, 0.f, 0.f, 0.f);
    const int beg = g_base[w];
    const int cnt = g_deg[w] - 1;

    for (int j = (g < 3) ? g : cnt; j < cnt; j += 3) {
        int2 m = g_meta[beg + j];
        float wgt = __int_as_float(m.y);
        float4 v = *(const float4*)(zp + (size_t)m.x * C + q * 4);
        acc.x = fmaf(wgt, v.x, acc.x);
        acc.y = fmaf(wgt, v.y, acc.y);
        acc.z = fmaf(wgt, v.z, acc.z);
        acc.w = fmaf(wgt, v.w, acc.w);
    }

    // cross-group reduce: lane q (<10) needs lanes q+10, q+20
    float sx1 = __shfl_sync(0xffffffffu, acc.x, lane + 10);
    float sy1 = __shfl_sync(0xffffffffu, acc.y, lane + 10);
    float sz1 = __shfl_sync(0xffffffffu, acc.z, lane + 10);
    float sw1 = __shfl_sync(0xffffffffu, acc.w, lane + 10);
    float sx2 = __shfl_sync(0xffffffffu, acc.x, lane + 20);
    float sy2 = __shfl_sync(0xffffffffu, acc.y, lane + 20);
    float sz2 = __shfl_sync(0xffffffffu, acc.z, lane + 20);
    float sw2 = __shfl_sync(0xffffffffu, acc.w, lane + 20);

    if (g == 0) {
        const size_t off = (size_t)w * C + q * 4;
        float d = g_dinv[w];
        float s = (1.0f - ALPHA) * d * d;
        float4 z0v = *(const float4*)(g_Z0 + off);
        float4 zpv = *(const float4*)(zp + off);
        float4 o;
        o.x = fmaf(s, zpv.x, ALPHA * z0v.x) + acc.x + sx1 + sx2;
        o.y = fmaf(s, zpv.y, ALPHA * z0v.y) + acc.y + sy1 + sy2;
        o.z = fmaf(s, zpv.z, ALPHA * z0v.z) + acc.z + sz1 + sz2;
        o.w = fmaf(s, zpv.w, ALPHA * z0v.w) + acc.w + sw1 + sw2;
        *(float4*)(out + off) = o;
    }
}

// ---------------- launch ----------------------------------------------------
extern "C" void kernel_launch(void* const* d_in, const int* in_sizes, int n_in,
                              void* d_out, int out_size) {
    const float* x  = (const float*)d_in[0];
    const float* W1 = (const float*)d_in[1];
    const float* b1 = (const float*)d_in[2];
    const float* W2 = (const float*)d_in[3];
    const float* b2 = (const float*)d_in[4];
    const int*   ei = (const int*)  d_in[5];
    float* out = (float*)d_out;

    float *Z0, *ZA, *ZB;
    cudaGetSymbolAddress((void**)&Z0, g_Z0);
    cudaGetSymbolAddress((void**)&ZA, g_ZA);
    cudaGetSymbolAddress((void**)&ZB, g_ZB);

    // k_mma at our launch index 3 (ncu -s 5 lands there)
    k_cvt_w1 <<<256, 1024>>>(W1);                                   // 0
    k_z0init <<<(N * 10 + 255) / 256, 256>>>(b2);                   // 1
    k_reset  <<<(N + 255) / 256, 256>>>();                          // 2

    cudaFuncSetAttribute(k_mma, cudaFuncAttributeMaxDynamicSharedMemorySize,
                         GEMM_SMEM);
    k_mma<<<(NPAD / 128) * 4, 256, GEMM_SMEM>>>(x, W2, b1);         // 3

    k_deg_count<<<(EDG + 255) / 256, 256>>>(ei);                    // 4
    k_dinv_base<<<(N + 255) / 256, 256>>>();                        // 5
    k_cursor   <<<(N + 255) / 256, 256>>>();                        // 6
    k_scatter  <<<(EDG + 255) / 256, 256>>>(ei);                    // 7

    const float* zp = Z0;
    for (int it = 1; it <= KITER; it++) {
        float* tgt = (it == KITER) ? out : ((it & 1) ? ZA : ZB);
        k_prop<<<(N * 32 + 255) / 256, 256>>>(zp, tgt);
        zp = tgt;
    }
}